// round 1
// baseline (speedup 1.0000x reference)
#include <cuda_runtime.h>

// Problem constants
#define B_    4
#define N_    32
#define H_    28
#define W_    28
#define D_    16
#define KK    3
#define HO    26
#define WO    26
#define O_    32
#define NI    288            // N*K*K input votes
#define ITERS 7

#define TPB   256
#define MST   33             // M stride (288 x 33)
#define VST   18             // Vf stride (288 x 18), float2-aligned
#define QST   17             // qf stride (32 x 17)

// smem layout (floats):
// patch 4608 | wcs 4608 | Vf 288*18=5184 | M 288*33=9504 | qfs 32*17=544 | uu 288 | vv 32 | red 256
#define SMEM_FLOATS (4608 + 4608 + 5184 + 9504 + 544 + 288 + 32 + 256)
#define SMEM_BYTES  (SMEM_FLOATS * 4)

__global__ __launch_bounds__(TPB) void sacaps_kernel(
    const float* __restrict__ inp,    // (4,32,28,28,16)
    const float* __restrict__ wcur,   // (3,3,32,4,4)
    const float* __restrict__ wnext,  // (32,4,4)
    const float* __restrict__ lns,    // (16,)
    const float* __restrict__ lnb,    // (16,)
    float* __restrict__ out)          // (4,32,26,26,16)
{
    extern __shared__ float sm[];
    float* patch = sm;                   // 4608, reused as Ps later
    float* wcs   = patch + 4608;         // 4608
    float* Vf    = wcs + 4608;           // 288*18
    float* Mm    = Vf + NI * VST;        // 288*33
    float* qfs   = Mm + NI * MST;        // 32*17
    float* uu    = qfs + 32 * QST;       // 288
    float* vv    = uu + NI;              // 32
    float* red   = vv + 32;              // 256

    const int t    = threadIdx.x;
    const int site = blockIdx.x;
    const int b    = site / (HO * WO);
    const int rem  = site - b * (HO * WO);
    const int hh   = rem / WO;
    const int ww   = rem - hh * WO;

    // ---- Stage weights + patch into smem ----
    // w_current (k,l,n,q,r) -> wcs[(n*9+kl)*16 + q*4+r]
    for (int g = t; g < 4608; g += TPB) {
        int kl = g >> 9;            // /512
        int n  = (g >> 4) & 31;
        int qr = g & 15;
        wcs[(n * 9 + kl) * 16 + qr] = wcur[g];
    }
    // w_next (o,q,r) -> qfs[o*17 + d]
    for (int g = t; g < 512; g += TPB) {
        int o = g >> 4, d = g & 15;
        qfs[o * QST + d] = wnext[g];
    }
    // input patch: patch[(n*9+kl)*16 + d] = inp[b,n,hh+k,ww+l,d]
    for (int e = t; e < 4608; e += TPB) {
        int n  = e / 144;
        int r  = e - n * 144;
        int kl = r >> 4;
        int d  = r & 15;
        int k  = kl / 3, l = kl - k * 3;
        patch[e] = inp[((((b * N_ + n) * H_) + hh + k) * W_ + (ww + l)) * D_ + d];
    }
    __syncthreads();

    // ---- Phase 1: Vf[i][p*4+r] = sum_q pose[p][q] * wcs[i][q*4+r] ----
    for (int e = t; e < 4608; e += TPB) {
        int i = e >> 4, d = e & 15;
        int p = d >> 2, r = d & 3;
        const float* pr = patch + i * 16 + p * 4;
        const float* wr = wcs + i * 16 + r;
        Vf[i * VST + d] = pr[0] * wr[0] + pr[1] * wr[4] + pr[2] * wr[8] + pr[3] * wr[12];
    }
    __syncthreads();

    // ---- Phase 2: M[i][o] = exp( (Vf[i] . qf[o]) / (sqrt(16)*0.75) ) ----
    {
        int o = t & 31;
        float qreg[16];
#pragma unroll
        for (int d = 0; d < 16; d++) qreg[d] = qfs[o * QST + d];
        int gi = t >> 5;
#pragma unroll 4
        for (int j = 0; j < 36; j++) {
            int i = j * 8 + gi;
            const float* vr = Vf + i * VST;
            float dot = 0.f;
#pragma unroll
            for (int d = 0; d < 16; d++) dot += vr[d] * qreg[d];
            Mm[i * MST + o] = __expf(dot * (1.0f / 3.0f));
        }
    }
    if (t < 32) vv[t] = 1.0f;
    __syncthreads();

    // ---- Phase 3: multiplicative Sinkhorn (exactly equiv. to log-domain ref) ----
    for (int it = 0; it < ITERS; it++) {
        // u_i = 1 / sum_o M[i][o] * v_o
        {
            const float* mr = Mm + t * MST;
            float s = 0.f;
#pragma unroll
            for (int o = 0; o < 32; o++) s += mr[o] * vv[o];
            uu[t] = 1.0f / s;
            if (t < 32) {
                const float* mr2 = Mm + (256 + t) * MST;
                float s2 = 0.f;
#pragma unroll
                for (int o = 0; o < 32; o++) s2 += mr2[o] * vv[o];
                uu[256 + t] = 1.0f / s2;
            }
        }
        __syncthreads();
        // v_o = 1 / sum_i u_i * M[i][o]
        {
            int o = t & 31, g = t >> 5;
            int i0 = g * 36;
            float s = 0.f;
#pragma unroll 4
            for (int i = i0; i < i0 + 36; i++) s += uu[i] * Mm[i * MST + o];
            red[t] = s;
        }
        __syncthreads();
        if (t < 32) {
            float s = 0.f;
#pragma unroll
            for (int g = 0; g < 8; g++) s += red[g * 32 + t];
            vv[t] = 1.0f / s;
        }
        __syncthreads();
    }

    // ---- Fold u into Vf ----
    for (int e = t; e < 4608; e += TPB) {
        int i = e >> 4, d = e & 15;
        Vf[i * VST + d] *= uu[i];
    }
    __syncthreads();

    // ---- Phase 4: P[o][d] = v_o * sum_i M[i][o] * (u_i Vf[i][d]) ----
    float* Ps = patch;  // reuse, stride VST
    {
        int o  = t >> 3;
        int d0 = (t & 7) * 2;
        float a0 = 0.f, a1 = 0.f;
#pragma unroll 4
        for (int i = 0; i < NI; i++) {
            float m = Mm[i * MST + o];
            float2 v = *(const float2*)(Vf + i * VST + d0);
            a0 += m * v.x;
            a1 += m * v.y;
        }
        float vo = vv[o];
        Ps[o * VST + d0]     = a0 * vo;
        Ps[o * VST + d0 + 1] = a1 * vo;
    }
    __syncthreads();

    // ---- Phase 5: out[o][p*4+r2] = sum_q P[o][p*4+q] * w_next[o][q*4+r2], then LN ----
    {
        int o  = t >> 3;
        int d0 = (t & 7) * 2;       // even; d0 and d0+1 share p
        int p  = d0 >> 2;
        int r2 = d0 & 3;
        const float* pp = Ps + o * VST + p * 4;
        const float* qq = qfs + o * QST;
        float x0 = 0.f, x1 = 0.f;
#pragma unroll
        for (int q = 0; q < 4; q++) {
            float pv = pp[q];
            x0 += pv * qq[q * 4 + r2];
            x1 += pv * qq[q * 4 + r2 + 1];
        }
        // layernorm over the 16 dims of this o (8-lane group, 2 vals each)
        float s = x0 + x1;
        s += __shfl_xor_sync(0xffffffffu, s, 1);
        s += __shfl_xor_sync(0xffffffffu, s, 2);
        s += __shfl_xor_sync(0xffffffffu, s, 4);
        float mu = s * (1.0f / 16.0f);
        float e0 = x0 - mu, e1 = x1 - mu;
        float ss = e0 * e0 + e1 * e1;
        ss += __shfl_xor_sync(0xffffffffu, ss, 1);
        ss += __shfl_xor_sync(0xffffffffu, ss, 2);
        ss += __shfl_xor_sync(0xffffffffu, ss, 4);
        float rstd = rsqrtf(ss * (1.0f / 16.0f) + 1e-5f);
        float y0 = e0 * rstd * lns[d0] + lnb[d0];
        float y1 = e1 * rstd * lns[d0 + 1] + lnb[d0 + 1];
        size_t oidx = ((((size_t)b * O_ + o) * HO + hh) * WO + ww) * D_ + d0;
        *(float2*)(out + oidx) = make_float2(y0, y1);
    }
}

extern "C" void kernel_launch(void* const* d_in, const int* in_sizes, int n_in,
                              void* d_out, int out_size)
{
    (void)in_sizes; (void)n_in; (void)out_size;
    cudaFuncSetAttribute(sacaps_kernel,
                         cudaFuncAttributeMaxDynamicSharedMemorySize, SMEM_BYTES);
    sacaps_kernel<<<B_ * HO * WO, TPB, SMEM_BYTES>>>(
        (const float*)d_in[0],   // input
        (const float*)d_in[1],   // w_current
        (const float*)d_in[2],   // w_next
        (const float*)d_in[3],   // ln_scale
        (const float*)d_in[4],   // ln_bias
        (float*)d_out);
}

// round 4
// speedup vs baseline: 1.1690x; 1.1690x over previous
#include <cuda_runtime.h>

// Problem constants
#define B_    4
#define N_    32
#define H_    28
#define W_    28
#define D_    16
#define HO    26
#define WO    26
#define O_    32
#define NI    288            // N*K*K votes
#define ITERS 7

#define TPB   256
#define MST   33             // M stride: row & column accesses conflict-free
#define VST   20             // Vf stride: float4-aligned (80B)
#define QST   17             // qf stride: conflict-free scalar

// smem floats: Vf 288*20=5760 | Mm 288*33=9504 | qfs 32*17=544 | uu 288 | vv 32 | red 256
#define SMEM_FLOATS (5760 + 9504 + 544 + 288 + 32 + 256)   // = 16384
#define SMEM_BYTES  (SMEM_FLOATS * 4)                      // = 65536

__global__ __launch_bounds__(TPB, 3) void sacaps_kernel(
    const float* __restrict__ inp,    // (4,32,28,28,16)
    const float* __restrict__ wcur,   // (3,3,32,4,4)
    const float* __restrict__ wnext,  // (32,4,4)
    const float* __restrict__ lns,    // (16,)
    const float* __restrict__ lnb,    // (16,)
    float* __restrict__ out)          // (4,32,26,26,16)
{
    extern __shared__ float sm[];
    float* Vf  = sm;                  // 288*20
    float* Mm  = Vf + NI * VST;       // 288*33
    float* qfs = Mm + NI * MST;       // 32*17
    float* uu  = qfs + 32 * QST;      // 288
    float* vv  = uu + NI;             // 32
    float* red = vv + 32;             // 256

    const int t    = threadIdx.x;
    const int site = blockIdx.x;
    const int b    = site / (HO * WO);
    const int rem  = site - b * (HO * WO);
    const int hh   = rem / WO;
    const int ww   = rem - hh * WO;

    // ---- stage w_next into smem (conflict-free stride 17) ----
    for (int g = t; g < 512; g += TPB) {
        int o = g >> 4, d = g & 15;
        qfs[o * QST + d] = wnext[g];
    }

    // ---- Phase 1: per-vote 4x4 matmul, direct from global, all in registers ----
    // Vf[i][p*4+r] = sum_q pose[i][p*4+q] * w[i][q*4+r],  i = n*9 + kl
    for (int i = t; i < NI; i += TPB) {
        int n  = i / 9;
        int kl = i - n * 9;
        int k  = kl / 3, l = kl - k * 3;
        const float4* pb = (const float4*)(inp +
            ((size_t)(((b * N_ + n) * H_) + hh + k) * W_ + (ww + l)) * D_);
        float4 p0 = pb[0], p1 = pb[1], p2 = pb[2], p3 = pb[3];
        const float4* wb = (const float4*)(wcur + kl * 512 + n * 16);
        float4 w0 = wb[0], w1 = wb[1], w2 = wb[2], w3 = wb[3];

        float4* vr = (float4*)(Vf + i * VST);
        {
            float4 v;
            v.x = p0.x*w0.x + p0.y*w1.x + p0.z*w2.x + p0.w*w3.x;
            v.y = p0.x*w0.y + p0.y*w1.y + p0.z*w2.y + p0.w*w3.y;
            v.z = p0.x*w0.z + p0.y*w1.z + p0.z*w2.z + p0.w*w3.z;
            v.w = p0.x*w0.w + p0.y*w1.w + p0.z*w2.w + p0.w*w3.w;
            vr[0] = v;
        }
        {
            float4 v;
            v.x = p1.x*w0.x + p1.y*w1.x + p1.z*w2.x + p1.w*w3.x;
            v.y = p1.x*w0.y + p1.y*w1.y + p1.z*w2.y + p1.w*w3.y;
            v.z = p1.x*w0.z + p1.y*w1.z + p1.z*w2.z + p1.w*w3.z;
            v.w = p1.x*w0.w + p1.y*w1.w + p1.z*w2.w + p1.w*w3.w;
            vr[1] = v;
        }
        {
            float4 v;
            v.x = p2.x*w0.x + p2.y*w1.x + p2.z*w2.x + p2.w*w3.x;
            v.y = p2.x*w0.y + p2.y*w1.y + p2.z*w2.y + p2.w*w3.y;
            v.z = p2.x*w0.z + p2.y*w1.z + p2.z*w2.z + p2.w*w3.z;
            v.w = p2.x*w0.w + p2.y*w1.w + p2.z*w2.w + p2.w*w3.w;
            vr[2] = v;
        }
        {
            float4 v;
            v.x = p3.x*w0.x + p3.y*w1.x + p3.z*w2.x + p3.w*w3.x;
            v.y = p3.x*w0.y + p3.y*w1.y + p3.z*w2.y + p3.w*w3.y;
            v.z = p3.x*w0.z + p3.y*w1.z + p3.z*w2.z + p3.w*w3.z;
            v.w = p3.x*w0.w + p3.y*w1.w + p3.z*w2.w + p3.w*w3.w;
            vr[3] = v;
        }
    }
    __syncthreads();

    // ---- Phase 2: M[i][o] = exp(dot(Vf[i], qf[o]) / 3) ----
    {
        int o = t & 31;
        int w = t >> 5;
        float q[16];
#pragma unroll
        for (int d = 0; d < 16; d++) q[d] = qfs[o * QST + d];
#pragma unroll 6
        for (int j = 0; j < 36; j++) {
            int i = w * 36 + j;
            const float4* vf4 = (const float4*)(Vf + i * VST);
            float4 a = vf4[0], bb = vf4[1], c = vf4[2], dd = vf4[3];
            float dot = a.x*q[0] + a.y*q[1] + a.z*q[2] + a.w*q[3]
                      + bb.x*q[4] + bb.y*q[5] + bb.z*q[6] + bb.w*q[7]
                      + c.x*q[8] + c.y*q[9] + c.z*q[10] + c.w*q[11]
                      + dd.x*q[12] + dd.y*q[13] + dd.z*q[14] + dd.w*q[15];
            Mm[i * MST + o] = __expf(dot * (1.0f / 3.0f));
        }
    }
    if (t < 32) vv[t] = 1.0f;
    __syncthreads();

    // ---- Phase 3: multiplicative Sinkhorn ----
    const float4* vv4 = (const float4*)vv;
    for (int it = 0; it < ITERS; it++) {
        // u_i = 1 / (M v)_i
        {
            const float* mr = Mm + t * MST;
            float s = 0.f;
#pragma unroll
            for (int c = 0; c < 8; c++) {
                float4 v = vv4[c];
                s += mr[4*c]*v.x + mr[4*c+1]*v.y + mr[4*c+2]*v.z + mr[4*c+3]*v.w;
            }
            uu[t] = __fdividef(1.0f, s);
            if (t < 32) {
                const float* mr2 = Mm + (256 + t) * MST;
                float s2 = 0.f;
#pragma unroll
                for (int c = 0; c < 8; c++) {
                    float4 v = vv4[c];
                    s2 += mr2[4*c]*v.x + mr2[4*c+1]*v.y + mr2[4*c+2]*v.z + mr2[4*c+3]*v.w;
                }
                uu[256 + t] = __fdividef(1.0f, s2);
            }
        }
        __syncthreads();
        // v_o = 1 / (M^T u)_o   (partials per 36-row group, then combine)
        {
            int o = t & 31, g = t >> 5;
            int i0 = g * 36;
            float s = 0.f;
#pragma unroll 4
            for (int i = i0; i < i0 + 36; i++) s += uu[i] * Mm[i * MST + o];
            red[t] = s;
        }
        __syncthreads();
        if (t < 32) {
            float s = 0.f;
#pragma unroll
            for (int g = 0; g < 8; g++) s += red[g * 32 + t];
            vv[t] = __fdividef(1.0f, s);
        }
        __syncthreads();
    }

    // ---- Phase 4+5 fused: P, w_next matmul, layernorm, store — all in registers ----
    {
        int o    = t >> 3;          // bits 3-7
        int quad = t & 3;           // bits 0-1
        int half = (t >> 2) & 1;    // bit 2
        int i0   = half * 144;
        float ax = 0.f, ay = 0.f, az = 0.f, aw = 0.f;
#pragma unroll 4
        for (int j = 0; j < 144; j++) {
            int i = i0 + j;
            float m = uu[i] * Mm[i * MST + o];
            float4 v = *(const float4*)(Vf + i * VST + quad * 4);
            ax += m * v.x; ay += m * v.y; az += m * v.z; aw += m * v.w;
        }
        // combine the two i-halves
        ax += __shfl_xor_sync(0xffffffffu, ax, 4);
        ay += __shfl_xor_sync(0xffffffffu, ay, 4);
        az += __shfl_xor_sync(0xffffffffu, az, 4);
        aw += __shfl_xor_sync(0xffffffffu, aw, 4);
        float vo = vv[o];
        ax *= vo; ay *= vo; az *= vo; aw *= vo;
        // this thread holds P[o][quad*4 .. quad*4+3] = row p=quad of next_pose
        // out[o][p*4+r] = sum_q P[o][p*4+q] * w_next[o][q*4+r]
        const float* qq = qfs + o * QST;
        float x0 = ax*qq[0] + ay*qq[4] + az*qq[8]  + aw*qq[12];
        float x1 = ax*qq[1] + ay*qq[5] + az*qq[9]  + aw*qq[13];
        float x2 = ax*qq[2] + ay*qq[6] + az*qq[10] + aw*qq[14];
        float x3 = ax*qq[3] + ay*qq[7] + az*qq[11] + aw*qq[15];
        // layernorm over d=16 (4 quads, lanes differing in bits 0-1)
        float s = x0 + x1 + x2 + x3;
        s += __shfl_xor_sync(0xffffffffu, s, 1);
        s += __shfl_xor_sync(0xffffffffu, s, 2);
        float mu = s * (1.0f / 16.0f);
        float e0 = x0 - mu, e1 = x1 - mu, e2 = x2 - mu, e3 = x3 - mu;
        float ss = e0*e0 + e1*e1 + e2*e2 + e3*e3;
        ss += __shfl_xor_sync(0xffffffffu, ss, 1);
        ss += __shfl_xor_sync(0xffffffffu, ss, 2);
        float rstd = rsqrtf(ss * (1.0f / 16.0f) + 1e-5f);
        int d0 = quad * 4;
        float y0 = e0 * rstd * __ldg(lns + d0)     + __ldg(lnb + d0);
        float y1 = e1 * rstd * __ldg(lns + d0 + 1) + __ldg(lnb + d0 + 1);
        float y2 = e2 * rstd * __ldg(lns + d0 + 2) + __ldg(lnb + d0 + 2);
        float y3 = e3 * rstd * __ldg(lns + d0 + 3) + __ldg(lnb + d0 + 3);
        if (half == 0) {
            size_t oidx = ((((size_t)b * O_ + o) * HO + hh) * WO + ww) * D_ + d0;
            *(float4*)(out + oidx) = make_float4(y0, y1, y2, y3);
        }
    }
}

extern "C" void kernel_launch(void* const* d_in, const int* in_sizes, int n_in,
                              void* d_out, int out_size)
{
    (void)in_sizes; (void)n_in; (void)out_size;
    cudaFuncSetAttribute(sacaps_kernel,
                         cudaFuncAttributeMaxDynamicSharedMemorySize, SMEM_BYTES);
    sacaps_kernel<<<B_ * HO * WO, TPB, SMEM_BYTES>>>(
        (const float*)d_in[0],   // input
        (const float*)d_in[1],   // w_current
        (const float*)d_in[2],   // w_next
        (const float*)d_in[3],   // ln_scale
        (const float*)d_in[4],   // ln_bias
        (float*)d_out);
}

// round 5
// speedup vs baseline: 1.7316x; 1.4813x over previous
#include <cuda_runtime.h>

// Problem constants
#define B_    4
#define N_    32
#define H_    28
#define W_    28
#define D_    16
#define HO    26
#define WO    26
#define O_    32
#define NI    288
#define ITERS 7

#define TPB   288            // 9 warps; thread t owns M row t
#define VST   20             // Vf stride, float4-aligned
#define MST   36             // scaled-M stride, float4-aligned, conflict-free col access
#define QST   20             // qf stride, float4-aligned

// smem floats: Vf 288*20=5760 (aliased as red2[9][32][20] in epilogue)
//            | Mm 288*36=10368 | qfs 32*20=640 | vv 32 | red 9*32=288
#define SMEM_FLOATS (5760 + 10368 + 640 + 32 + 288)   // 17088
#define SMEM_BYTES  (SMEM_FLOATS * 4)                 // 68352 -> 3 CTAs/SM

__global__ __launch_bounds__(TPB, 3) void sacaps_kernel(
    const float* __restrict__ inp,    // (4,32,28,28,16)
    const float* __restrict__ wcur,   // (3,3,32,4,4)
    const float* __restrict__ wnext,  // (32,4,4)
    const float* __restrict__ lns,    // (16,)
    const float* __restrict__ lnb,    // (16,)
    float* __restrict__ out)          // (4,32,26,26,16)
{
    extern __shared__ float sm[];
    float* Vf  = sm;                  // 288*20; later aliased as red2
    float* Mm  = Vf + NI * VST;       // 288*36 (u-prescaled M, written post-Sinkhorn)
    float* qfs = Mm + NI * MST;       // 32*20
    float* vv  = qfs + 32 * QST;      // 32
    float* red = vv + 32;             // 9*32

    const int t    = threadIdx.x;
    const int lane = t & 31;
    const int wid  = t >> 5;
    const int site = blockIdx.x;
    const int b    = site / (HO * WO);
    const int rem  = site - b * (HO * WO);
    const int hh   = rem / WO;
    const int ww   = rem - hh * WO;

    // ---- stage w_next into smem, stride 20 (float4-aligned) ----
    for (int g = t; g < 512; g += TPB) {
        int o = g >> 4, d = g & 15;
        qfs[o * QST + d] = wnext[g];
    }

    // ---- Phase 1: vote t = (n, kl): 4x4 matmul from global -> Vf row t ----
    {
        int n  = t / 9;
        int kl = t - n * 9;
        int k  = kl / 3, l = kl - k * 3;
        const float4* pb = (const float4*)(inp +
            ((size_t)(((b * N_ + n) * H_) + hh + k) * W_ + (ww + l)) * D_);
        float4 p0 = pb[0], p1 = pb[1], p2 = pb[2], p3 = pb[3];
        const float4* wb = (const float4*)(wcur + kl * 512 + n * 16);
        float4 w0 = wb[0], w1 = wb[1], w2 = wb[2], w3 = wb[3];
        float4* vr = (float4*)(Vf + t * VST);
        float4 v;
        v.x = p0.x*w0.x + p0.y*w1.x + p0.z*w2.x + p0.w*w3.x;
        v.y = p0.x*w0.y + p0.y*w1.y + p0.z*w2.y + p0.w*w3.y;
        v.z = p0.x*w0.z + p0.y*w1.z + p0.z*w2.z + p0.w*w3.z;
        v.w = p0.x*w0.w + p0.y*w1.w + p0.z*w2.w + p0.w*w3.w;
        vr[0] = v;
        v.x = p1.x*w0.x + p1.y*w1.x + p1.z*w2.x + p1.w*w3.x;
        v.y = p1.x*w0.y + p1.y*w1.y + p1.z*w2.y + p1.w*w3.y;
        v.z = p1.x*w0.z + p1.y*w1.z + p1.z*w2.z + p1.w*w3.z;
        v.w = p1.x*w0.w + p1.y*w1.w + p1.z*w2.w + p1.w*w3.w;
        vr[1] = v;
        v.x = p2.x*w0.x + p2.y*w1.x + p2.z*w2.x + p2.w*w3.x;
        v.y = p2.x*w0.y + p2.y*w1.y + p2.z*w2.y + p2.w*w3.y;
        v.z = p2.x*w0.z + p2.y*w1.z + p2.z*w2.z + p2.w*w3.z;
        v.w = p2.x*w0.w + p2.y*w1.w + p2.z*w2.w + p2.w*w3.w;
        vr[2] = v;
        v.x = p3.x*w0.x + p3.y*w1.x + p3.z*w2.x + p3.w*w3.x;
        v.y = p3.x*w0.y + p3.y*w1.y + p3.z*w2.y + p3.w*w3.y;
        v.z = p3.x*w0.z + p3.y*w1.z + p3.z*w2.z + p3.w*w3.z;
        v.w = p3.x*w0.w + p3.y*w1.w + p3.z*w2.w + p3.w*w3.w;
        vr[3] = v;
    }
    __syncthreads();

    // ---- Phase 2: m[o] = exp(dot(Vf[t], qf[o]) / 3), row t resident in regs ----
    float m[32];
    {
        const float4* vr = (const float4*)(Vf + t * VST);
        float4 f0 = vr[0], f1 = vr[1], f2 = vr[2], f3 = vr[3];
#pragma unroll 4
        for (int o = 0; o < 32; o++) {
            const float4* qp = (const float4*)(qfs + o * QST);
            float4 q0 = qp[0], q1 = qp[1], q2 = qp[2], q3 = qp[3];
            float dot = f0.x*q0.x + f0.y*q0.y + f0.z*q0.z + f0.w*q0.w
                      + f1.x*q1.x + f1.y*q1.y + f1.z*q1.z + f1.w*q1.w
                      + f2.x*q2.x + f2.y*q2.y + f2.z*q2.z + f2.w*q2.w
                      + f3.x*q3.x + f3.y*q3.y + f3.z*q3.z + f3.w*q3.w;
            m[o] = __expf(dot * (1.0f / 3.0f));
        }
    }

    // ---- Phase 3: multiplicative Sinkhorn, M register-resident ----
    float u = 0.f;
    for (int it = 0; it < ITERS; it++) {
        // u = 1 / (M v)_t    (iter 0: v == 1)
        float s = 0.f;
        if (it == 0) {
#pragma unroll
            for (int o = 0; o < 32; o++) s += m[o];
        } else {
            const float4* v4 = (const float4*)vv;
#pragma unroll
            for (int c = 0; c < 8; c++) {
                float4 v = v4[c];
                s += m[4*c]*v.x + m[4*c+1]*v.y + m[4*c+2]*v.z + m[4*c+3]*v.w;
            }
        }
        u = __fdividef(1.0f, s);

        // column sums: warp halving reduction; lane l ends with col l partial
        float w16[16];
#pragma unroll
        for (int k = 0; k < 16; k++) {
            float sendv = (lane & 16) ? m[k] : m[k + 16];
            float keep  = (lane & 16) ? m[k + 16] : m[k];
            w16[k] = u * keep + __shfl_xor_sync(0xffffffffu, u * sendv, 16);
        }
#pragma unroll
        for (int k = 0; k < 8; k++) {
            float sendv = (lane & 8) ? w16[k] : w16[k + 8];
            float keep  = (lane & 8) ? w16[k + 8] : w16[k];
            w16[k] = keep + __shfl_xor_sync(0xffffffffu, sendv, 8);
        }
#pragma unroll
        for (int k = 0; k < 4; k++) {
            float sendv = (lane & 4) ? w16[k] : w16[k + 4];
            float keep  = (lane & 4) ? w16[k + 4] : w16[k];
            w16[k] = keep + __shfl_xor_sync(0xffffffffu, sendv, 4);
        }
#pragma unroll
        for (int k = 0; k < 2; k++) {
            float sendv = (lane & 2) ? w16[k] : w16[k + 2];
            float keep  = (lane & 2) ? w16[k + 2] : w16[k];
            w16[k] = keep + __shfl_xor_sync(0xffffffffu, sendv, 2);
        }
        {
            float sendv = (lane & 1) ? w16[0] : w16[1];
            float keep  = (lane & 1) ? w16[1] : w16[0];
            w16[0] = keep + __shfl_xor_sync(0xffffffffu, sendv, 1);
        }
        red[wid * 32 + lane] = w16[0];
        __syncthreads();
        if (t < 32) {
            float cs = 0.f;
#pragma unroll
            for (int g = 0; g < 9; g++) cs += red[g * 32 + t];
            vv[t] = __fdividef(1.0f, cs);
        }
        __syncthreads();
    }

    // ---- write u-prescaled M row to smem (stride 36, STS.128) ----
    {
        float4* mr = (float4*)(Mm + t * MST);
#pragma unroll
        for (int c = 0; c < 8; c++)
            mr[c] = make_float4(u*m[4*c], u*m[4*c+1], u*m[4*c+2], u*m[4*c+3]);
    }
    __syncthreads();

    // ---- Phase 4 stage 1: warp wid sums rows [wid*32, wid*32+32), lane = o ----
    float4 a0 = {0,0,0,0}, a1 = {0,0,0,0}, a2 = {0,0,0,0}, a3 = {0,0,0,0};
    {
        int base = wid * 32;
#pragma unroll 4
        for (int j = 0; j < 32; j++) {
            int i = base + j;
            float am = Mm[i * MST + lane];
            const float4* vr = (const float4*)(Vf + i * VST);
            float4 v0 = vr[0], v1 = vr[1], v2 = vr[2], v3 = vr[3];
            a0.x += am*v0.x; a0.y += am*v0.y; a0.z += am*v0.z; a0.w += am*v0.w;
            a1.x += am*v1.x; a1.y += am*v1.y; a1.z += am*v1.z; a1.w += am*v1.w;
            a2.x += am*v2.x; a2.y += am*v2.y; a2.z += am*v2.z; a2.w += am*v2.w;
            a3.x += am*v3.x; a3.y += am*v3.y; a3.z += am*v3.z; a3.w += am*v3.w;
        }
    }
    __syncthreads();   // all Vf reads done; now alias Vf as red2[wid][o][20]
    {
        float4* r2 = (float4*)(Vf + (wid * 32 + lane) * VST);
        r2[0] = a0; r2[1] = a1; r2[2] = a2; r2[3] = a3;
    }
    __syncthreads();

    // ---- Phase 4 stage 2: combine 9 chunks, apply v_o, w_next matmul, LN, store ----
    if (t < 128) {
        int o = t >> 2, quad = t & 3;
        float4 p = {0,0,0,0};
#pragma unroll
        for (int g = 0; g < 9; g++) {
            float4 c = *(const float4*)(Vf + (g * 32 + o) * VST + quad * 4);
            p.x += c.x; p.y += c.y; p.z += c.z; p.w += c.w;
        }
        float vo = vv[o];
        float ax = p.x * vo, ay = p.y * vo, az = p.z * vo, aw = p.w * vo;
        // out[o][quad*4+r] = sum_q P[o][quad*4+q] * w_next[o][q*4+r]
        const float* qq = qfs + o * QST;
        float x0 = ax*qq[0] + ay*qq[4] + az*qq[8]  + aw*qq[12];
        float x1 = ax*qq[1] + ay*qq[5] + az*qq[9]  + aw*qq[13];
        float x2 = ax*qq[2] + ay*qq[6] + az*qq[10] + aw*qq[14];
        float x3 = ax*qq[3] + ay*qq[7] + az*qq[11] + aw*qq[15];
        // layernorm over the 16 dims of o (4 lanes = 4 quads)
        float s = x0 + x1 + x2 + x3;
        s += __shfl_xor_sync(0xffffffffu, s, 1);
        s += __shfl_xor_sync(0xffffffffu, s, 2);
        float mu = s * (1.0f / 16.0f);
        float e0 = x0 - mu, e1 = x1 - mu, e2 = x2 - mu, e3 = x3 - mu;
        float ss = e0*e0 + e1*e1 + e2*e2 + e3*e3;
        ss += __shfl_xor_sync(0xffffffffu, ss, 1);
        ss += __shfl_xor_sync(0xffffffffu, ss, 2);
        float rstd = rsqrtf(ss * (1.0f / 16.0f) + 1e-5f);
        int d0 = quad * 4;
        float y0 = e0 * rstd * __ldg(lns + d0)     + __ldg(lnb + d0);
        float y1 = e1 * rstd * __ldg(lns + d0 + 1) + __ldg(lnb + d0 + 1);
        float y2 = e2 * rstd * __ldg(lns + d0 + 2) + __ldg(lnb + d0 + 2);
        float y3 = e3 * rstd * __ldg(lns + d0 + 3) + __ldg(lnb + d0 + 3);
        size_t oidx = ((((size_t)b * O_ + o) * HO + hh) * WO + ww) * D_ + d0;
        *(float4*)(out + oidx) = make_float4(y0, y1, y2, y3);
    }
}

extern "C" void kernel_launch(void* const* d_in, const int* in_sizes, int n_in,
                              void* d_out, int out_size)
{
    (void)in_sizes; (void)n_in; (void)out_size;
    cudaFuncSetAttribute(sacaps_kernel,
                         cudaFuncAttributeMaxDynamicSharedMemorySize, SMEM_BYTES);
    sacaps_kernel<<<B_ * HO * WO, TPB, SMEM_BYTES>>>(
        (const float*)d_in[0],   // input
        (const float*)d_in[1],   // w_current
        (const float*)d_in[2],   // w_next
        (const float*)d_in[3],   // ln_scale
        (const float*)d_in[4],   // ln_bias
        (float*)d_out);
}

// round 8
// speedup vs baseline: 1.9252x; 1.1118x over previous
#include <cuda_runtime.h>
#include <cstdint>

// Problem constants
#define B_    4
#define N_    32
#define H_    28
#define W_    28
#define D_    16
#define HO    26
#define WO    26
#define O_    32
#define NI    288
#define ITERS 7

#define TPB   288            // 9 warps; thread t owns M row t
#define VST   20             // Vf stride (floats), 80B rows, 16B aligned
#define MST   36             // scaled-M stride, 144B rows, 16B aligned
#define QST   20             // qf stride

// smem floats: Vf 288*20=5760 (aliased as red2 in epilogue)
//            | Mm 288*36=10368 | qfs 32*20=640 | vv 32 | red 9*32=288
#define VF_OFF   0
#define MM_OFF   5760
#define QF_OFF   (5760 + 10368)          // 16128
#define VV_OFF   (QF_OFF + 640)          // 16768
#define RED_OFF  (VV_OFF + 32)           // 16800
#define SMEM_FLOATS (RED_OFF + 288)      // 17088
#define SMEM_BYTES  (SMEM_FLOATS * 4)    // 68352 -> 3 CTAs/SM

typedef unsigned long long u64;

__device__ __forceinline__ u64 pack2(float lo, float hi) {
    u64 d; asm("mov.b64 %0, {%1, %2};" : "=l"(d) : "f"(lo), "f"(hi)); return d;
}
__device__ __forceinline__ void unpack2(float& lo, float& hi, u64 s) {
    asm("mov.b64 {%0, %1}, %2;" : "=f"(lo), "=f"(hi) : "l"(s));
}
__device__ __forceinline__ u64 fma2(u64 a, u64 b, u64 c) {
    u64 d; asm("fma.rn.f32x2 %0, %1, %2, %3;" : "=l"(d) : "l"(a), "l"(b), "l"(c)); return d;
}
__device__ __forceinline__ u64 mul2(u64 a, u64 b) {
    u64 d; asm("mul.rn.f32x2 %0, %1, %2;" : "=l"(d) : "l"(a), "l"(b)); return d;
}
__device__ __forceinline__ u64 add2(u64 a, u64 b) {
    u64 d; asm("add.rn.f32x2 %0, %1, %2;" : "=l"(d) : "l"(a), "l"(b)); return d;
}
__device__ __forceinline__ void lds2(u64& a, u64& b, uint32_t addr) {
    asm volatile("ld.shared.v2.u64 {%0, %1}, [%2];" : "=l"(a), "=l"(b) : "r"(addr) : "memory");
}
__device__ __forceinline__ void sts2(uint32_t addr, u64 a, u64 b) {
    asm volatile("st.shared.v2.u64 [%0], {%1, %2};" :: "r"(addr), "l"(a), "l"(b) : "memory");
}
__device__ __forceinline__ float ex2f(float x) {
    float r; asm("ex2.approx.f32 %0, %1;" : "=f"(r) : "f"(x)); return r;
}

__global__ __launch_bounds__(TPB, 3) void sacaps_kernel(
    const float* __restrict__ inp,    // (4,32,28,28,16)
    const float* __restrict__ wcur,   // (3,3,32,4,4)
    const float* __restrict__ wnext,  // (32,4,4)
    const float* __restrict__ lns,    // (16,)
    const float* __restrict__ lnb,    // (16,)
    float* __restrict__ out)          // (4,32,26,26,16)
{
    extern __shared__ float sm[];
    const uint32_t sb   = (uint32_t)__cvta_generic_to_shared(sm);
    const uint32_t vf_b = sb + VF_OFF * 4;
    const uint32_t mm_b = sb + MM_OFF * 4;
    const uint32_t qf_b = sb + QF_OFF * 4;
    float* Vf  = sm + VF_OFF;
    float* Mm  = sm + MM_OFF;
    float* qfs = sm + QF_OFF;
    float* vv  = sm + VV_OFF;
    float* red = sm + RED_OFF;

    const int t    = threadIdx.x;
    const int lane = t & 31;
    const int wid  = t >> 5;
    const int site = blockIdx.x;
    const int b    = site / (HO * WO);
    const int rem  = site - b * (HO * WO);
    const int hh   = rem / WO;
    const int ww   = rem - hh * WO;

    // ---- stage w_next into smem ----
    for (int g = t; g < 512; g += TPB) {
        int o = g >> 4, d = g & 15;
        qfs[o * QST + d] = wnext[g];
    }

    // ---- Phase 1: vote t: 4x4 matmul from global; row kept in regs AND stored ----
    u64 f2[8];
    {
        int n  = t / 9;
        int kl = t - n * 9;
        int k  = kl / 3, l = kl - k * 3;
        const float4* pb = (const float4*)(inp +
            ((size_t)(((b * N_ + n) * H_) + hh + k) * W_ + (ww + l)) * D_);
        float4 p0 = pb[0], p1 = pb[1], p2 = pb[2], p3 = pb[3];
        const float4* wb = (const float4*)(wcur + kl * 512 + n * 16);
        float4 w0 = wb[0], w1 = wb[1], w2 = wb[2], w3 = wb[3];
        float vx, vy, vz, vw;
        vx = p0.x*w0.x + p0.y*w1.x + p0.z*w2.x + p0.w*w3.x;
        vy = p0.x*w0.y + p0.y*w1.y + p0.z*w2.y + p0.w*w3.y;
        vz = p0.x*w0.z + p0.y*w1.z + p0.z*w2.z + p0.w*w3.z;
        vw = p0.x*w0.w + p0.y*w1.w + p0.z*w2.w + p0.w*w3.w;
        f2[0] = pack2(vx, vy); f2[1] = pack2(vz, vw);
        vx = p1.x*w0.x + p1.y*w1.x + p1.z*w2.x + p1.w*w3.x;
        vy = p1.x*w0.y + p1.y*w1.y + p1.z*w2.y + p1.w*w3.y;
        vz = p1.x*w0.z + p1.y*w1.z + p1.z*w2.z + p1.w*w3.z;
        vw = p1.x*w0.w + p1.y*w1.w + p1.z*w2.w + p1.w*w3.w;
        f2[2] = pack2(vx, vy); f2[3] = pack2(vz, vw);
        vx = p2.x*w0.x + p2.y*w1.x + p2.z*w2.x + p2.w*w3.x;
        vy = p2.x*w0.y + p2.y*w1.y + p2.z*w2.y + p2.w*w3.y;
        vz = p2.x*w0.z + p2.y*w1.z + p2.z*w2.z + p2.w*w3.z;
        vw = p2.x*w0.w + p2.y*w1.w + p2.z*w2.w + p2.w*w3.w;
        f2[4] = pack2(vx, vy); f2[5] = pack2(vz, vw);
        vx = p3.x*w0.x + p3.y*w1.x + p3.z*w2.x + p3.w*w3.x;
        vy = p3.x*w0.y + p3.y*w1.y + p3.z*w2.y + p3.w*w3.y;
        vz = p3.x*w0.z + p3.y*w1.z + p3.z*w2.z + p3.w*w3.z;
        vw = p3.x*w0.w + p3.y*w1.w + p3.z*w2.w + p3.w*w3.w;
        f2[6] = pack2(vx, vy); f2[7] = pack2(vz, vw);
        uint32_t va = vf_b + (uint32_t)(t * VST) * 4;
        sts2(va,      f2[0], f2[1]);
        sts2(va + 16, f2[2], f2[3]);
        sts2(va + 32, f2[4], f2[5]);
        sts2(va + 48, f2[6], f2[7]);
    }
    __syncthreads();   // qfs visible

    // ---- Phase 2: m[o] = exp2( C * dot(Vf[t], qf[o]) ), C = log2(e)/3 ----
    u64 m2[16];
    {
        const float C = 0.4808983469629878f;  // log2(e)/3
        u64 Cp = pack2(C, C);
#pragma unroll
        for (int j = 0; j < 8; j++) f2[j] = mul2(f2[j], Cp);
        float mlo = 0.f;
#pragma unroll
        for (int o = 0; o < 32; o++) {
            uint32_t qa = qf_b + (uint32_t)(o * QST) * 4;
            u64 q0, q1, q2, q3;
            lds2(q0, q1, qa);
            lds2(q2, q3, qa + 16);
            u64 aA = mul2(f2[0], q0);
            u64 aB = mul2(f2[1], q1);
            aA = fma2(f2[2], q2, aA);
            aB = fma2(f2[3], q3, aB);
            lds2(q0, q1, qa + 32);
            lds2(q2, q3, qa + 48);
            aA = fma2(f2[4], q0, aA);
            aB = fma2(f2[5], q1, aB);
            aA = fma2(f2[6], q2, aA);
            aB = fma2(f2[7], q3, aB);
            u64 aa = add2(aA, aB);
            float lo, hi; unpack2(lo, hi, aa);
            float val = ex2f(lo + hi);
            if (o & 1) m2[o >> 1] = pack2(mlo, val); else mlo = val;
        }
    }

    // ---- Phase 3: multiplicative Sinkhorn, M register-resident (packed) ----
    float u = 0.f;
    for (int it = 0; it < ITERS; it++) {
        float s;
        if (it == 0) {
            u64 aA = add2(m2[0], m2[2]);
            u64 aB = add2(m2[1], m2[3]);
#pragma unroll
            for (int j = 4; j < 16; j += 2) {
                aA = add2(aA, m2[j]);
                aB = add2(aB, m2[j + 1]);
            }
            u64 aa = add2(aA, aB);
            float lo, hi; unpack2(lo, hi, aa);
            s = lo + hi;
        } else {
            uint32_t va = sb + VV_OFF * 4;
            u64 p0, p1, p2, p3;
            lds2(p0, p1, va);
            lds2(p2, p3, va + 16);
            u64 aA = mul2(m2[0], p0);
            u64 aB = mul2(m2[1], p1);
            aA = fma2(m2[2], p2, aA);
            aB = fma2(m2[3], p3, aB);
            lds2(p0, p1, va + 32);
            lds2(p2, p3, va + 48);
            aA = fma2(m2[4], p0, aA);
            aB = fma2(m2[5], p1, aB);
            aA = fma2(m2[6], p2, aA);
            aB = fma2(m2[7], p3, aB);
            lds2(p0, p1, va + 64);
            lds2(p2, p3, va + 80);
            aA = fma2(m2[8], p0, aA);
            aB = fma2(m2[9], p1, aB);
            aA = fma2(m2[10], p2, aA);
            aB = fma2(m2[11], p3, aB);
            lds2(p0, p1, va + 96);
            lds2(p2, p3, va + 112);
            aA = fma2(m2[12], p0, aA);
            aB = fma2(m2[13], p1, aB);
            aA = fma2(m2[14], p2, aA);
            aB = fma2(m2[15], p3, aB);
            u64 aa = add2(aA, aB);
            float lo, hi; unpack2(lo, hi, aa);
            s = lo + hi;
        }
        u = __fdividef(1.0f, s);

        // column sums via pair butterfly: lane l ends with colsum[l] partial
        u64 up = pack2(u, u);
        u64 w2[8];
#pragma unroll
        for (int j = 0; j < 8; j++) {
            u64 a = mul2(m2[j], up);
            u64 bq = mul2(m2[j + 8], up);
            u64 keep = (lane & 16) ? bq : a;
            u64 send = (lane & 16) ? a : bq;
            w2[j] = add2(keep, __shfl_xor_sync(0xffffffffu, send, 16));
        }
#pragma unroll
        for (int j = 0; j < 4; j++) {
            u64 keep = (lane & 8) ? w2[j + 4] : w2[j];
            u64 send = (lane & 8) ? w2[j] : w2[j + 4];
            w2[j] = add2(keep, __shfl_xor_sync(0xffffffffu, send, 8));
        }
#pragma unroll
        for (int j = 0; j < 2; j++) {
            u64 keep = (lane & 4) ? w2[j + 2] : w2[j];
            u64 send = (lane & 4) ? w2[j] : w2[j + 2];
            w2[j] = add2(keep, __shfl_xor_sync(0xffffffffu, send, 4));
        }
        {
            u64 keep = (lane & 2) ? w2[1] : w2[0];
            u64 send = (lane & 2) ? w2[0] : w2[1];
            w2[0] = add2(keep, __shfl_xor_sync(0xffffffffu, send, 2));
        }
        float lo, hi; unpack2(lo, hi, w2[0]);
        float kp = (lane & 1) ? hi : lo;
        float sd = (lane & 1) ? lo : hi;
        float res = kp + __shfl_xor_sync(0xffffffffu, sd, 1);
        red[wid * 32 + lane] = res;
        __syncthreads();
        if (t < 32) {
            float cs = 0.f;
#pragma unroll
            for (int g = 0; g < 9; g++) cs += red[g * 32 + t];
            vv[t] = __fdividef(1.0f, cs);
        }
        __syncthreads();
    }

    // ---- write u-prescaled M row to smem ----
    {
        u64 up = pack2(u, u);
        uint32_t ma = mm_b + (uint32_t)(t * MST) * 4;
#pragma unroll
        for (int c = 0; c < 16; c += 2)
            sts2(ma + c * 8, mul2(m2[c], up), mul2(m2[c + 1], up));
    }
    __syncthreads();

    // ---- Phase 4 stage 1: warp wid sums rows [wid*32, +32), lane = o ----
    u64 acc2[8];
#pragma unroll
    for (int c = 0; c < 8; c++) acc2[c] = 0ULL;   // {0.f, 0.f}
    {
        int base = wid * 32;
#pragma unroll 4
        for (int j = 0; j < 32; j++) {
            int i = base + j;
            float am = Mm[i * MST + lane];
            u64 amp = pack2(am, am);
            uint32_t va = vf_b + (uint32_t)(i * VST) * 4;
            u64 v0, v1, v2, v3;
            lds2(v0, v1, va);
            lds2(v2, v3, va + 16);
            acc2[0] = fma2(amp, v0, acc2[0]);
            acc2[1] = fma2(amp, v1, acc2[1]);
            acc2[2] = fma2(amp, v2, acc2[2]);
            acc2[3] = fma2(amp, v3, acc2[3]);
            lds2(v0, v1, va + 32);
            lds2(v2, v3, va + 48);
            acc2[4] = fma2(amp, v0, acc2[4]);
            acc2[5] = fma2(amp, v1, acc2[5]);
            acc2[6] = fma2(amp, v2, acc2[6]);
            acc2[7] = fma2(amp, v3, acc2[7]);
        }
    }
    __syncthreads();   // all Vf reads done; alias Vf as red2[wid][o][20]
    {
        uint32_t ra = vf_b + (uint32_t)((wid * 32 + lane) * VST) * 4;
        sts2(ra,      acc2[0], acc2[1]);
        sts2(ra + 16, acc2[2], acc2[3]);
        sts2(ra + 32, acc2[4], acc2[5]);
        sts2(ra + 48, acc2[6], acc2[7]);
    }
    __syncthreads();

    // ---- Phase 4 stage 2: combine 9 chunks, v_o, w_next matmul, LN, store ----
    if (t < 128) {
        int o = t >> 2, quad = t & 3;
        float4 p = {0.f, 0.f, 0.f, 0.f};
#pragma unroll
        for (int g = 0; g < 9; g++) {
            float4 c = *(const float4*)(Vf + (g * 32 + o) * VST + quad * 4);
            p.x += c.x; p.y += c.y; p.z += c.z; p.w += c.w;
        }
        float vo = vv[o];
        float ax = p.x * vo, ay = p.y * vo, az = p.z * vo, aw = p.w * vo;
        const float* qq = qfs + o * QST;
        float x0 = ax*qq[0] + ay*qq[4] + az*qq[8]  + aw*qq[12];
        float x1 = ax*qq[1] + ay*qq[5] + az*qq[9]  + aw*qq[13];
        float x2 = ax*qq[2] + ay*qq[6] + az*qq[10] + aw*qq[14];
        float x3 = ax*qq[3] + ay*qq[7] + az*qq[11] + aw*qq[15];
        float s = x0 + x1 + x2 + x3;
        s += __shfl_xor_sync(0xffffffffu, s, 1);
        s += __shfl_xor_sync(0xffffffffu, s, 2);
        float mu = s * (1.0f / 16.0f);
        float e0 = x0 - mu, e1 = x1 - mu, e2 = x2 - mu, e3 = x3 - mu;
        float ss = e0*e0 + e1*e1 + e2*e2 + e3*e3;
        ss += __shfl_xor_sync(0xffffffffu, ss, 1);
        ss += __shfl_xor_sync(0xffffffffu, ss, 2);
        float rstd = rsqrtf(ss * (1.0f / 16.0f) + 1e-5f);
        int d0 = quad * 4;
        float y0 = e0 * rstd * __ldg(lns + d0)     + __ldg(lnb + d0);
        float y1 = e1 * rstd * __ldg(lns + d0 + 1) + __ldg(lnb + d0 + 1);
        float y2 = e2 * rstd * __ldg(lns + d0 + 2) + __ldg(lnb + d0 + 2);
        float y3 = e3 * rstd * __ldg(lns + d0 + 3) + __ldg(lnb + d0 + 3);
        size_t oidx = ((((size_t)b * O_ + o) * HO + hh) * WO + ww) * D_ + d0;
        *(float4*)(out + oidx) = make_float4(y0, y1, y2, y3);
    }
}

extern "C" void kernel_launch(void* const* d_in, const int* in_sizes, int n_in,
                              void* d_out, int out_size)
{
    (void)in_sizes; (void)n_in; (void)out_size;
    cudaFuncSetAttribute(sacaps_kernel,
                         cudaFuncAttributeMaxDynamicSharedMemorySize, SMEM_BYTES);
    sacaps_kernel<<<B_ * HO * WO, TPB, SMEM_BYTES>>>(
        (const float*)d_in[0],   // input
        (const float*)d_in[1],   // w_current
        (const float*)d_in[2],   // w_next
        (const float*)d_in[3],   // ln_scale
        (const float*)d_in[4],   // ln_bias
        (float*)d_out);
}

// round 9
// speedup vs baseline: 2.1780x; 1.1313x over previous
#include <cuda_runtime.h>
#include <cstdint>

// Problem constants
#define B_    4
#define N_    32
#define H_    28
#define W_    28
#define D_    16
#define HO    26
#define WO    26
#define O_    32
#define NI    288
#define ITERS 7

#define TPB   288            // 9 warps; thread t owns M row t
#define VST   20             // Vf stride (floats), 80B rows, 16B aligned
#define MST   36             // scaled-M stride, 144B rows, 16B aligned
#define QST   20             // qf stride

// smem floats: Vf 288*20=5760 (aliased as red2 in epilogue)
//            | Mm 288*36=10368 | qfs 32*20=640 | vv 32 | red 9*32=288
#define VF_OFF   0
#define MM_OFF   5760
#define QF_OFF   (5760 + 10368)          // 16128
#define VV_OFF   (QF_OFF + 640)          // 16768
#define RED_OFF  (VV_OFF + 32)           // 16800
#define SMEM_FLOATS (RED_OFF + 288)      // 17088
#define SMEM_BYTES  (SMEM_FLOATS * 4)    // 68352 -> 3 CTAs/SM

typedef unsigned long long u64;

__device__ __forceinline__ u64 pack2(float lo, float hi) {
    u64 d; asm("mov.b64 %0, {%1, %2};" : "=l"(d) : "f"(lo), "f"(hi)); return d;
}
__device__ __forceinline__ void unpack2(float& lo, float& hi, u64 s) {
    asm("mov.b64 {%0, %1}, %2;" : "=f"(lo), "=f"(hi) : "l"(s));
}
__device__ __forceinline__ u64 fma2(u64 a, u64 b, u64 c) {
    u64 d; asm("fma.rn.f32x2 %0, %1, %2, %3;" : "=l"(d) : "l"(a), "l"(b), "l"(c)); return d;
}
__device__ __forceinline__ u64 mul2(u64 a, u64 b) {
    u64 d; asm("mul.rn.f32x2 %0, %1, %2;" : "=l"(d) : "l"(a), "l"(b)); return d;
}
__device__ __forceinline__ u64 add2(u64 a, u64 b) {
    u64 d; asm("add.rn.f32x2 %0, %1, %2;" : "=l"(d) : "l"(a), "l"(b)); return d;
}
__device__ __forceinline__ void lds2(u64& a, u64& b, uint32_t addr) {
    asm volatile("ld.shared.v2.u64 {%0, %1}, [%2];" : "=l"(a), "=l"(b) : "r"(addr) : "memory");
}
__device__ __forceinline__ void sts2(uint32_t addr, u64 a, u64 b) {
    asm volatile("st.shared.v2.u64 [%0], {%1, %2};" :: "r"(addr), "l"(a), "l"(b) : "memory");
}
__device__ __forceinline__ float ex2f(float x) {
    float r; asm("ex2.approx.f32 %0, %1;" : "=f"(r) : "f"(x)); return r;
}

__global__ __launch_bounds__(TPB, 3) void sacaps_kernel(
    const float* __restrict__ inp,    // (4,32,28,28,16)
    const float* __restrict__ wcur,   // (3,3,32,4,4)
    const float* __restrict__ wnext,  // (32,4,4)
    const float* __restrict__ lns,    // (16,)
    const float* __restrict__ lnb,    // (16,)
    float* __restrict__ out)          // (4,32,26,26,16)
{
    extern __shared__ float sm[];
    const uint32_t sb   = (uint32_t)__cvta_generic_to_shared(sm);
    const uint32_t vf_b = sb + VF_OFF * 4;
    const uint32_t mm_b = sb + MM_OFF * 4;
    const uint32_t qf_b = sb + QF_OFF * 4;
    float* Vf  = sm + VF_OFF;
    float* qfs = sm + QF_OFF;
    float* vv  = sm + VV_OFF;
    float* red = sm + RED_OFF;

    const int t    = threadIdx.x;
    const int lane = t & 31;
    const int wid  = t >> 5;
    const int site = blockIdx.x;
    const int b    = site / (HO * WO);
    const int rem  = site - b * (HO * WO);
    const int hh   = rem / WO;
    const int ww   = rem - hh * WO;

    // ---- stage w_next into smem ----
    for (int g = t; g < 512; g += TPB) {
        int o = g >> 4, d = g & 15;
        qfs[o * QST + d] = wnext[g];
    }

    // ---- Phase 1: vote t: 4x4 matmul from global; row kept in regs AND stored ----
    u64 f2[8];
    {
        int n  = t / 9;
        int kl = t - n * 9;
        int k  = kl / 3, l = kl - k * 3;
        const float4* pb = (const float4*)(inp +
            ((size_t)(((b * N_ + n) * H_) + hh + k) * W_ + (ww + l)) * D_);
        float4 p0 = pb[0], p1 = pb[1], p2 = pb[2], p3 = pb[3];
        const float4* wb = (const float4*)(wcur + kl * 512 + n * 16);
        float4 w0 = wb[0], w1 = wb[1], w2 = wb[2], w3 = wb[3];
        float vx, vy, vz, vw;
        vx = p0.x*w0.x + p0.y*w1.x + p0.z*w2.x + p0.w*w3.x;
        vy = p0.x*w0.y + p0.y*w1.y + p0.z*w2.y + p0.w*w3.y;
        vz = p0.x*w0.z + p0.y*w1.z + p0.z*w2.z + p0.w*w3.z;
        vw = p0.x*w0.w + p0.y*w1.w + p0.z*w2.w + p0.w*w3.w;
        f2[0] = pack2(vx, vy); f2[1] = pack2(vz, vw);
        vx = p1.x*w0.x + p1.y*w1.x + p1.z*w2.x + p1.w*w3.x;
        vy = p1.x*w0.y + p1.y*w1.y + p1.z*w2.y + p1.w*w3.y;
        vz = p1.x*w0.z + p1.y*w1.z + p1.z*w2.z + p1.w*w3.z;
        vw = p1.x*w0.w + p1.y*w1.w + p1.z*w2.w + p1.w*w3.w;
        f2[2] = pack2(vx, vy); f2[3] = pack2(vz, vw);
        vx = p2.x*w0.x + p2.y*w1.x + p2.z*w2.x + p2.w*w3.x;
        vy = p2.x*w0.y + p2.y*w1.y + p2.z*w2.y + p2.w*w3.y;
        vz = p2.x*w0.z + p2.y*w1.z + p2.z*w2.z + p2.w*w3.z;
        vw = p2.x*w0.w + p2.y*w1.w + p2.z*w2.w + p2.w*w3.w;
        f2[4] = pack2(vx, vy); f2[5] = pack2(vz, vw);
        vx = p3.x*w0.x + p3.y*w1.x + p3.z*w2.x + p3.w*w3.x;
        vy = p3.x*w0.y + p3.y*w1.y + p3.z*w2.y + p3.w*w3.y;
        vz = p3.x*w0.z + p3.y*w1.z + p3.z*w2.z + p3.w*w3.z;
        vw = p3.x*w0.w + p3.y*w1.w + p3.z*w2.w + p3.w*w3.w;
        f2[6] = pack2(vx, vy); f2[7] = pack2(vz, vw);
        uint32_t va = vf_b + (uint32_t)(t * VST) * 4;
        sts2(va,      f2[0], f2[1]);
        sts2(va + 16, f2[2], f2[3]);
        sts2(va + 32, f2[4], f2[5]);
        sts2(va + 48, f2[6], f2[7]);
    }
    __syncthreads();   // qfs visible

    // ---- Phase 2: m[o] = exp2( C * dot(Vf[t], qf[o]) ), C = log2(e)/3 ----
    u64 m2[16];
    {
        const float C = 0.4808983469629878f;  // log2(e)/3
        u64 Cp = pack2(C, C);
#pragma unroll
        for (int j = 0; j < 8; j++) f2[j] = mul2(f2[j], Cp);
        float mlo = 0.f;
#pragma unroll
        for (int o = 0; o < 32; o++) {
            uint32_t qa = qf_b + (uint32_t)(o * QST) * 4;
            u64 q0, q1, q2, q3;
            lds2(q0, q1, qa);
            lds2(q2, q3, qa + 16);
            u64 aA = mul2(f2[0], q0);
            u64 aB = mul2(f2[1], q1);
            aA = fma2(f2[2], q2, aA);
            aB = fma2(f2[3], q3, aB);
            lds2(q0, q1, qa + 32);
            lds2(q2, q3, qa + 48);
            aA = fma2(f2[4], q0, aA);
            aB = fma2(f2[5], q1, aB);
            aA = fma2(f2[6], q2, aA);
            aB = fma2(f2[7], q3, aB);
            u64 aa = add2(aA, aB);
            float lo, hi; unpack2(lo, hi, aa);
            float val = ex2f(lo + hi);
            if (o & 1) m2[o >> 1] = pack2(mlo, val); else mlo = val;
        }
    }

    // ---- Phase 3: multiplicative Sinkhorn, M register-resident (packed) ----
    float u = 0.f;
    for (int it = 0; it < ITERS; it++) {
        float s;
        if (it == 0) {
            u64 aA = add2(m2[0], m2[2]);
            u64 aB = add2(m2[1], m2[3]);
#pragma unroll
            for (int j = 4; j < 16; j += 2) {
                aA = add2(aA, m2[j]);
                aB = add2(aB, m2[j + 1]);
            }
            u64 aa = add2(aA, aB);
            float lo, hi; unpack2(lo, hi, aa);
            s = lo + hi;
        } else {
            uint32_t va = sb + VV_OFF * 4;
            u64 p0, p1, p2, p3;
            lds2(p0, p1, va);
            lds2(p2, p3, va + 16);
            u64 aA = mul2(m2[0], p0);
            u64 aB = mul2(m2[1], p1);
            aA = fma2(m2[2], p2, aA);
            aB = fma2(m2[3], p3, aB);
            lds2(p0, p1, va + 32);
            lds2(p2, p3, va + 48);
            aA = fma2(m2[4], p0, aA);
            aB = fma2(m2[5], p1, aB);
            aA = fma2(m2[6], p2, aA);
            aB = fma2(m2[7], p3, aB);
            lds2(p0, p1, va + 64);
            lds2(p2, p3, va + 80);
            aA = fma2(m2[8], p0, aA);
            aB = fma2(m2[9], p1, aB);
            aA = fma2(m2[10], p2, aA);
            aB = fma2(m2[11], p3, aB);
            lds2(p0, p1, va + 96);
            lds2(p2, p3, va + 112);
            aA = fma2(m2[12], p0, aA);
            aB = fma2(m2[13], p1, aB);
            aA = fma2(m2[14], p2, aA);
            aB = fma2(m2[15], p3, aB);
            u64 aa = add2(aA, aB);
            float lo, hi; unpack2(lo, hi, aa);
            s = lo + hi;
        }
        u = __fdividef(1.0f, s);

        // column sums via pair butterfly: lane l ends with colsum[l] partial
        u64 up = pack2(u, u);
        u64 w2[8];
#pragma unroll
        for (int j = 0; j < 8; j++) {
            u64 a = mul2(m2[j], up);
            u64 bq = mul2(m2[j + 8], up);
            u64 keep = (lane & 16) ? bq : a;
            u64 send = (lane & 16) ? a : bq;
            w2[j] = add2(keep, __shfl_xor_sync(0xffffffffu, send, 16));
        }
#pragma unroll
        for (int j = 0; j < 4; j++) {
            u64 keep = (lane & 8) ? w2[j + 4] : w2[j];
            u64 send = (lane & 8) ? w2[j] : w2[j + 4];
            w2[j] = add2(keep, __shfl_xor_sync(0xffffffffu, send, 8));
        }
#pragma unroll
        for (int j = 0; j < 2; j++) {
            u64 keep = (lane & 4) ? w2[j + 2] : w2[j];
            u64 send = (lane & 4) ? w2[j] : w2[j + 2];
            w2[j] = add2(keep, __shfl_xor_sync(0xffffffffu, send, 4));
        }
        {
            u64 keep = (lane & 2) ? w2[1] : w2[0];
            u64 send = (lane & 2) ? w2[0] : w2[1];
            w2[0] = add2(keep, __shfl_xor_sync(0xffffffffu, send, 2));
        }
        float lo, hi; unpack2(lo, hi, w2[0]);
        float kp = (lane & 1) ? hi : lo;
        float sd = (lane & 1) ? lo : hi;
        float res = kp + __shfl_xor_sync(0xffffffffu, sd, 1);
        red[wid * 32 + lane] = res;
        __syncthreads();
        if (t < 32) {
            float cs = 0.f;
#pragma unroll
            for (int g = 0; g < 9; g++) cs += red[g * 32 + t];
            vv[t] = __fdividef(1.0f, cs);
        }
        __syncthreads();
    }

    // ---- write u-prescaled M row to smem, PERMUTED layout [i][o_lo][oh] ----
    // position (o_lo*4 + oh) holds mhat[o_lo + 8*oh]
    {
        float ms[32];
#pragma unroll
        for (int j = 0; j < 16; j++) unpack2(ms[2 * j], ms[2 * j + 1], m2[j]);
        uint32_t ma = mm_b + (uint32_t)(t * MST) * 4;
#pragma unroll
        for (int olo = 0; olo < 8; olo++) {
            u64 a  = pack2(u * ms[olo],      u * ms[olo + 8]);
            u64 bq = pack2(u * ms[olo + 16], u * ms[olo + 24]);
            sts2(ma + olo * 16, a, bq);
        }
    }
    __syncthreads();

    // ---- Phase 4 stage 1: lane=(o_lo, dq); per-row reads: 1 Vf-quad + 1 Mhat-quad ----
    // acc2[oh*2], acc2[oh*2+1] = P_partial[o_lo + 8*oh][dq*4 .. dq*4+3]
    const int olo = lane & 7;
    const int dq  = lane >> 3;       // 0..3
    u64 acc2[8];
#pragma unroll
    for (int c = 0; c < 8; c++) acc2[c] = 0ULL;
    {
        int base = wid * 32;
        uint32_t vq = vf_b + (uint32_t)(base * VST + dq * 4) * 4;
        uint32_t mq = mm_b + (uint32_t)(base * MST) * 4 + (uint32_t)(olo * 16);
#pragma unroll 4
        for (int j = 0; j < 32; j++) {
            u64 v0, v1, mh0, mh1;
            lds2(v0, v1, vq + (uint32_t)(j * VST) * 4);
            lds2(mh0, mh1, mq + (uint32_t)(j * MST) * 4);
            float ma0, ma1, ma2, ma3;
            unpack2(ma0, ma1, mh0);
            unpack2(ma2, ma3, mh1);
            u64 b0 = pack2(ma0, ma0);
            u64 b1 = pack2(ma1, ma1);
            u64 b2 = pack2(ma2, ma2);
            u64 b3 = pack2(ma3, ma3);
            acc2[0] = fma2(b0, v0, acc2[0]);
            acc2[1] = fma2(b0, v1, acc2[1]);
            acc2[2] = fma2(b1, v0, acc2[2]);
            acc2[3] = fma2(b1, v1, acc2[3]);
            acc2[4] = fma2(b2, v0, acc2[4]);
            acc2[5] = fma2(b2, v1, acc2[5]);
            acc2[6] = fma2(b3, v0, acc2[6]);
            acc2[7] = fma2(b3, v1, acc2[7]);
        }
    }
    __syncthreads();   // all Vf reads done; alias Vf as red2[wid][o][20]
#pragma unroll
    for (int oh = 0; oh < 4; oh++) {
        int o = olo + 8 * oh;
        uint32_t ra = vf_b + (uint32_t)(((wid * 32 + o) * VST + dq * 4)) * 4;
        sts2(ra, acc2[oh * 2], acc2[oh * 2 + 1]);
    }
    __syncthreads();

    // ---- Phase 4 stage 2: combine 9 chunks, v_o, w_next matmul, LN, store ----
    if (t < 128) {
        int o = t >> 2, quad = t & 3;
        float4 p = {0.f, 0.f, 0.f, 0.f};
#pragma unroll
        for (int g = 0; g < 9; g++) {
            float4 c = *(const float4*)(Vf + (g * 32 + o) * VST + quad * 4);
            p.x += c.x; p.y += c.y; p.z += c.z; p.w += c.w;
        }
        float vo = vv[o];
        float ax = p.x * vo, ay = p.y * vo, az = p.z * vo, aw = p.w * vo;
        const float* qq = qfs + o * QST;
        float x0 = ax*qq[0] + ay*qq[4] + az*qq[8]  + aw*qq[12];
        float x1 = ax*qq[1] + ay*qq[5] + az*qq[9]  + aw*qq[13];
        float x2 = ax*qq[2] + ay*qq[6] + az*qq[10] + aw*qq[14];
        float x3 = ax*qq[3] + ay*qq[7] + az*qq[11] + aw*qq[15];
        float s = x0 + x1 + x2 + x3;
        s += __shfl_xor_sync(0xffffffffu, s, 1);
        s += __shfl_xor_sync(0xffffffffu, s, 2);
        float mu = s * (1.0f / 16.0f);
        float e0 = x0 - mu, e1 = x1 - mu, e2 = x2 - mu, e3 = x3 - mu;
        float ss = e0*e0 + e1*e1 + e2*e2 + e3*e3;
        ss += __shfl_xor_sync(0xffffffffu, ss, 1);
        ss += __shfl_xor_sync(0xffffffffu, ss, 2);
        float rstd = rsqrtf(ss * (1.0f / 16.0f) + 1e-5f);
        int d0 = quad * 4;
        float y0 = e0 * rstd * __ldg(lns + d0)     + __ldg(lnb + d0);
        float y1 = e1 * rstd * __ldg(lns + d0 + 1) + __ldg(lnb + d0 + 1);
        float y2 = e2 * rstd * __ldg(lns + d0 + 2) + __ldg(lnb + d0 + 2);
        float y3 = e3 * rstd * __ldg(lns + d0 + 3) + __ldg(lnb + d0 + 3);
        size_t oidx = ((((size_t)b * O_ + o) * HO + hh) * WO + ww) * D_ + d0;
        *(float4*)(out + oidx) = make_float4(y0, y1, y2, y3);
    }
}

extern "C" void kernel_launch(void* const* d_in, const int* in_sizes, int n_in,
                              void* d_out, int out_size)
{
    (void)in_sizes; (void)n_in; (void)out_size;
    cudaFuncSetAttribute(sacaps_kernel,
                         cudaFuncAttributeMaxDynamicSharedMemorySize, SMEM_BYTES);
    sacaps_kernel<<<B_ * HO * WO, TPB, SMEM_BYTES>>>(
        (const float*)d_in[0],   // input
        (const float*)d_in[1],   // w_current
        (const float*)d_in[2],   // w_next
        (const float*)d_in[3],   // ln_scale
        (const float*)d_in[4],   // ln_bias
        (float*)d_out);
}